// round 3
// baseline (speedup 1.0000x reference)
#include <cuda_runtime.h>
#include <cuda_bf16.h>
#include <cstdint>

// Problem constants (from reference setup_inputs)
#define BATCH  4096
#define CWDIM  1024
#define CODES  128     // C
#define BOOK   256     // K
#define DEMB   8       // D

#define THREADS 128
#define RPT     4                      // rows per thread
#define ROWS_PB (THREADS * RPT)        // 512 rows per block

// Packed fp32x2 helpers (sm_103a)
#define FMA2(acc, a, b) \
    asm("fma.rn.f32x2 %0, %1, %2, %0;" : "+l"(acc) : "l"(a), "l"(b))
#define UNPACK2(lo, hi, v) \
    asm("mov.b64 {%0, %1}, %2;" : "=f"(lo), "=f"(hi) : "l"(v))

static __device__ __forceinline__ unsigned long long pack2f(float a, float b) {
    unsigned long long r;
    asm("mov.b64 %0, {%1, %2};" : "=l"(r) : "f"(a), "f"(b));
    return r;
}

// ---------------------------------------------------------------------------
// Fused kernel. grid = (BATCH/512, CODES), block = 128 threads, one c each.
// Each thread handles 4 b-rows (2 packed row-pairs via f32x2).
// score(k) = 0.5*||c_k||^2 - x . c_k  (same argmin as full distance)
// ---------------------------------------------------------------------------
__global__ void __launch_bounds__(THREADS)
vq_fused_kernel(const float* __restrict__ x,
                const float* __restrict__ cb,
                float* __restrict__ cw_embed,
                float* __restrict__ one_hot)
{
    __shared__ float4             s_cb[BOOK * 2];      // 8 KB  plain codebook[c]
    __shared__ unsigned long long s_dup[BOOK * 8];     // 16 KB splatted (c,c) pairs
    __shared__ unsigned long long s_h2[BOOK];          // 2 KB  splatted 0.5*||c||^2
    __shared__ unsigned char      s_idx[ROWS_PB];      // argmin index per local row

    const int c = blockIdx.y;
    const int t = threadIdx.x;

    // ---- Stage codebook[c]: plain + splatted (2 codes per thread) ----
    const float4* cb4 = reinterpret_cast<const float4*>(cb + (size_t)c * BOOK * DEMB);
    #pragma unroll
    for (int kk = t; kk < BOOK; kk += THREADS) {
        float4 r0 = cb4[2 * kk + 0];
        float4 r1 = cb4[2 * kk + 1];
        s_cb[2 * kk + 0] = r0;
        s_cb[2 * kk + 1] = r1;
        float h = 0.5f * (r0.x * r0.x + r0.y * r0.y + r0.z * r0.z + r0.w * r0.w +
                          r1.x * r1.x + r1.y * r1.y + r1.z * r1.z + r1.w * r1.w);
        s_h2[kk] = pack2f(h, h);
        s_dup[kk * 8 + 0] = pack2f(r0.x, r0.x);
        s_dup[kk * 8 + 1] = pack2f(r0.y, r0.y);
        s_dup[kk * 8 + 2] = pack2f(r0.z, r0.z);
        s_dup[kk * 8 + 3] = pack2f(r0.w, r0.w);
        s_dup[kk * 8 + 4] = pack2f(r1.x, r1.x);
        s_dup[kk * 8 + 5] = pack2f(r1.y, r1.y);
        s_dup[kk * 8 + 6] = pack2f(r1.z, r1.z);
        s_dup[kk * 8 + 7] = pack2f(r1.w, r1.w);
    }
    __syncthreads();

    const int b0 = blockIdx.x * ROWS_PB;

    // ---- Load x for 4 rows, negate & pack across row-pairs ----
    // row i (i=0..3) = b0 + t + i*128 ; pair p packs rows (2p, 2p+1)
    unsigned long long xn[2][8];
    #pragma unroll
    for (int p = 0; p < 2; ++p) {
        const int rA = b0 + t + (2 * p) * THREADS;
        const int rB = rA + THREADS;
        const float4* pa = reinterpret_cast<const float4*>(x + (size_t)rA * CWDIM + c * DEMB);
        const float4* pb = reinterpret_cast<const float4*>(x + (size_t)rB * CWDIM + c * DEMB);
        float4 a0 = pa[0], a1 = pa[1];
        float4 e0 = pb[0], e1 = pb[1];
        xn[p][0] = pack2f(-a0.x, -e0.x);
        xn[p][1] = pack2f(-a0.y, -e0.y);
        xn[p][2] = pack2f(-a0.z, -e0.z);
        xn[p][3] = pack2f(-a0.w, -e0.w);
        xn[p][4] = pack2f(-a1.x, -e1.x);
        xn[p][5] = pack2f(-a1.y, -e1.y);
        xn[p][6] = pack2f(-a1.z, -e1.z);
        xn[p][7] = pack2f(-a1.w, -e1.w);
    }

    float best0 = 3.4e38f, best1 = 3.4e38f, best2 = 3.4e38f, best3 = 3.4e38f;
    int   bi0 = 0, bi1 = 0, bi2 = 0, bi3 = 0;

    const ulonglong2* dup2 = reinterpret_cast<const ulonglong2*>(s_dup);

    #pragma unroll 4
    for (int k = 0; k < BOOK; ++k) {
        const unsigned long long h = s_h2[k];
        ulonglong2 q0 = dup2[k * 4 + 0];
        ulonglong2 q1 = dup2[k * 4 + 1];
        ulonglong2 q2 = dup2[k * 4 + 2];
        ulonglong2 q3 = dup2[k * 4 + 3];

        unsigned long long a0 = h, a1 = h;
        FMA2(a0, xn[0][0], q0.x);  FMA2(a1, xn[1][0], q0.x);
        FMA2(a0, xn[0][1], q0.y);  FMA2(a1, xn[1][1], q0.y);
        FMA2(a0, xn[0][2], q1.x);  FMA2(a1, xn[1][2], q1.x);
        FMA2(a0, xn[0][3], q1.y);  FMA2(a1, xn[1][3], q1.y);
        FMA2(a0, xn[0][4], q2.x);  FMA2(a1, xn[1][4], q2.x);
        FMA2(a0, xn[0][5], q2.y);  FMA2(a1, xn[1][5], q2.y);
        FMA2(a0, xn[0][6], q3.x);  FMA2(a1, xn[1][6], q3.x);
        FMA2(a0, xn[0][7], q3.y);  FMA2(a1, xn[1][7], q3.y);

        float s0, s1, s2, s3;
        UNPACK2(s0, s1, a0);
        UNPACK2(s2, s3, a1);

        // strict < keeps FIRST minimum (matches jnp.argmin tie-break)
        if (s0 < best0) { best0 = s0; bi0 = k; }
        if (s1 < best1) { best1 = s1; bi1 = k; }
        if (s2 < best2) { best2 = s2; bi2 = k; }
        if (s3 < best3) { best3 = s3; bi3 = k; }
    }

    // ---- record indices + write cw_embed for the 4 rows ----
    s_idx[t + 0 * THREADS] = (unsigned char)bi0;
    s_idx[t + 1 * THREADS] = (unsigned char)bi1;
    s_idx[t + 2 * THREADS] = (unsigned char)bi2;
    s_idx[t + 3 * THREADS] = (unsigned char)bi3;

    {
        const int bis[4] = {bi0, bi1, bi2, bi3};
        #pragma unroll
        for (int i = 0; i < 4; ++i) {
            const int rb = b0 + t + i * THREADS;
            float4* o = reinterpret_cast<float4*>(cw_embed + (size_t)rb * CWDIM + c * DEMB);
            o[0] = s_cb[2 * bis[i] + 0];
            o[1] = s_cb[2 * bis[i] + 1];
        }
    }

    __syncthreads();

    // ---- one_hot fill: 512 local rows x 256 floats (64 float4 per row).
    // 128 threads -> 2 rows per iteration, 256 iterations, fully coalesced.
    const int off  = t & 63;   // float4 slot (covers k = off*4 .. off*4+3)
    const int rsub = t >> 6;   // 0..1

    float4* oh4 = reinterpret_cast<float4*>(one_hot)
                + (size_t)(b0 + rsub) * (CODES * BOOK / 4)
                + (size_t)c * (BOOK / 4)
                + off;
    const size_t step4 = (size_t)2 * (CODES * BOOK / 4);
    const unsigned kb = (unsigned)off * 4u;

    #pragma unroll 4
    for (int it = 0; it < ROWS_PB / 2; ++it) {
        const unsigned idx = s_idx[it * 2 + rsub];
        float4 v;
        v.x = (idx == kb + 0u) ? 1.0f : 0.0f;
        v.y = (idx == kb + 1u) ? 1.0f : 0.0f;
        v.z = (idx == kb + 2u) ? 1.0f : 0.0f;
        v.w = (idx == kb + 3u) ? 1.0f : 0.0f;
        *oh4 = v;
        oh4 += step4;
    }
}

// ---------------------------------------------------------------------------
extern "C" void kernel_launch(void* const* d_in, const int* in_sizes, int n_in,
                              void* d_out, int out_size)
{
    const float* x  = (const float*)d_in[0];   // [4096, 1024]
    const float* cb = (const float*)d_in[1];   // [128, 256, 8]

    float* cw_embed = (float*)d_out;                               // [4096, 1024]
    float* one_hot  = (float*)d_out + (size_t)BATCH * CWDIM;       // [4096, 128, 256]

    dim3 grid(BATCH / ROWS_PB, CODES);
    vq_fused_kernel<<<grid, THREADS>>>(x, cb, cw_embed, one_hot);
}